// round 2
// baseline (speedup 1.0000x reference)
#include <cuda_runtime.h>

// x[256, 4096, 32] -> out[256, 64, 64, 32]  (GADF)
#define BATCH 256
#define TLEN  4096
#define CH    32
#define PAA   64
#define BINSZ 64   // TLEN / PAA

// One block per batch element, 512 threads = 16 warps, 4 CTAs/SM.
//
// Read phase: warp w owns t in [256w, 256w+256) = bins 4w..4w+3.
//   lane -> (t_off = lane>>3 in [0,4), c4 = lane&7).  Each iter k loads
//   float4 at x[b, 256w + 4k + t_off, c4*4] -> warp reads 512B contiguous
//   (LDG.128). Bin index = k>>4 is k-uniform. 4 bin-sums + min/max in regs.
// Cross-lane reduce: xor-8/16 shuffles collapse the 4 t_off copies.
// Write phase: thread owns (j = tid>>3, c4 = tid&7), loops i=0..63,
//   STG.128, 512B contiguous per warp.
__global__ __launch_bounds__(512, 4)
void gaf_gadf_kernel(const float* __restrict__ x, float* __restrict__ out) {
    __shared__ float sp[PAA][CH];      // bin sums -> p   (8 KB)
    __shared__ float sy[PAA][CH];      // y               (8 KB)
    __shared__ float smmn[16][36];     // per-warp per-channel min (16B-aligned rows)
    __shared__ float smmx[16][36];
    __shared__ float smin[CH];
    __shared__ float smax[CH];

    const int tid   = threadIdx.x;
    const int lane  = tid & 31;
    const int warp  = tid >> 5;        // 0..15
    const int t_off = lane >> 3;       // 0..3
    const int c4    = (lane & 7) * 4;  // channel group start
    const int b     = blockIdx.x;

    const float* xb = x + (size_t)b * (TLEN * CH);

    // ---------------- Read phase ----------------
    {
        const float* base = xb + (size_t)(256 * warp + t_off) * CH + c4;
        float4 s0 = {0,0,0,0}, s1 = {0,0,0,0}, s2 = {0,0,0,0}, s3 = {0,0,0,0};
        float4 vmin = { 3.4e38f,  3.4e38f,  3.4e38f,  3.4e38f};
        float4 vmax = {-3.4e38f, -3.4e38f, -3.4e38f, -3.4e38f};

        #pragma unroll 4
        for (int k = 0; k < 16; ++k) {
            float4 v = __ldcs((const float4*)(base + (size_t)(4 * k) * CH));
            s0.x += v.x; s0.y += v.y; s0.z += v.z; s0.w += v.w;
            vmin.x = fminf(vmin.x, v.x); vmin.y = fminf(vmin.y, v.y);
            vmin.z = fminf(vmin.z, v.z); vmin.w = fminf(vmin.w, v.w);
            vmax.x = fmaxf(vmax.x, v.x); vmax.y = fmaxf(vmax.y, v.y);
            vmax.z = fmaxf(vmax.z, v.z); vmax.w = fmaxf(vmax.w, v.w);
        }
        #pragma unroll 4
        for (int k = 16; k < 32; ++k) {
            float4 v = __ldcs((const float4*)(base + (size_t)(4 * k) * CH));
            s1.x += v.x; s1.y += v.y; s1.z += v.z; s1.w += v.w;
            vmin.x = fminf(vmin.x, v.x); vmin.y = fminf(vmin.y, v.y);
            vmin.z = fminf(vmin.z, v.z); vmin.w = fminf(vmin.w, v.w);
            vmax.x = fmaxf(vmax.x, v.x); vmax.y = fmaxf(vmax.y, v.y);
            vmax.z = fmaxf(vmax.z, v.z); vmax.w = fmaxf(vmax.w, v.w);
        }
        #pragma unroll 4
        for (int k = 32; k < 48; ++k) {
            float4 v = __ldcs((const float4*)(base + (size_t)(4 * k) * CH));
            s2.x += v.x; s2.y += v.y; s2.z += v.z; s2.w += v.w;
            vmin.x = fminf(vmin.x, v.x); vmin.y = fminf(vmin.y, v.y);
            vmin.z = fminf(vmin.z, v.z); vmin.w = fminf(vmin.w, v.w);
            vmax.x = fmaxf(vmax.x, v.x); vmax.y = fmaxf(vmax.y, v.y);
            vmax.z = fmaxf(vmax.z, v.z); vmax.w = fmaxf(vmax.w, v.w);
        }
        #pragma unroll 4
        for (int k = 48; k < 64; ++k) {
            float4 v = __ldcs((const float4*)(base + (size_t)(4 * k) * CH));
            s3.x += v.x; s3.y += v.y; s3.z += v.z; s3.w += v.w;
            vmin.x = fminf(vmin.x, v.x); vmin.y = fminf(vmin.y, v.y);
            vmin.z = fminf(vmin.z, v.z); vmin.w = fminf(vmin.w, v.w);
            vmax.x = fmaxf(vmax.x, v.x); vmax.y = fmaxf(vmax.y, v.y);
            vmax.z = fmaxf(vmax.z, v.z); vmax.w = fmaxf(vmax.w, v.w);
        }

        // Collapse the 4 t_off copies (lanes xor 8, 16). Componentwise.
        #pragma unroll
        for (int o = 8; o <= 16; o <<= 1) {
            s0.x += __shfl_xor_sync(~0u, s0.x, o); s0.y += __shfl_xor_sync(~0u, s0.y, o);
            s0.z += __shfl_xor_sync(~0u, s0.z, o); s0.w += __shfl_xor_sync(~0u, s0.w, o);
            s1.x += __shfl_xor_sync(~0u, s1.x, o); s1.y += __shfl_xor_sync(~0u, s1.y, o);
            s1.z += __shfl_xor_sync(~0u, s1.z, o); s1.w += __shfl_xor_sync(~0u, s1.w, o);
            s2.x += __shfl_xor_sync(~0u, s2.x, o); s2.y += __shfl_xor_sync(~0u, s2.y, o);
            s2.z += __shfl_xor_sync(~0u, s2.z, o); s2.w += __shfl_xor_sync(~0u, s2.w, o);
            s3.x += __shfl_xor_sync(~0u, s3.x, o); s3.y += __shfl_xor_sync(~0u, s3.y, o);
            s3.z += __shfl_xor_sync(~0u, s3.z, o); s3.w += __shfl_xor_sync(~0u, s3.w, o);
            vmin.x = fminf(vmin.x, __shfl_xor_sync(~0u, vmin.x, o));
            vmin.y = fminf(vmin.y, __shfl_xor_sync(~0u, vmin.y, o));
            vmin.z = fminf(vmin.z, __shfl_xor_sync(~0u, vmin.z, o));
            vmin.w = fminf(vmin.w, __shfl_xor_sync(~0u, vmin.w, o));
            vmax.x = fmaxf(vmax.x, __shfl_xor_sync(~0u, vmax.x, o));
            vmax.y = fmaxf(vmax.y, __shfl_xor_sync(~0u, vmax.y, o));
            vmax.z = fmaxf(vmax.z, __shfl_xor_sync(~0u, vmax.z, o));
            vmax.w = fmaxf(vmax.w, __shfl_xor_sync(~0u, vmax.w, o));
        }
        if (t_off == 0) {  // lanes 0..7 hold reduced values for channels c4..c4+3
            *(float4*)&sp[4 * warp + 0][c4] = s0;
            *(float4*)&sp[4 * warp + 1][c4] = s1;
            *(float4*)&sp[4 * warp + 2][c4] = s2;
            *(float4*)&sp[4 * warp + 3][c4] = s3;
            *(float4*)&smmn[warp][c4] = vmin;
            *(float4*)&smmx[warp][c4] = vmax;
        }
    }
    __syncthreads();

    // ---------------- Final min/max over 16 warps ----------------
    if (tid < CH) {
        float m = smmn[0][tid], M = smmx[0][tid];
        #pragma unroll
        for (int w = 1; w < 16; ++w) {
            m = fminf(m, smmn[w][tid]);
            M = fmaxf(M, smmx[w][tid]);
        }
        smin[tid] = m;
        smax[tid] = M;
    }
    __syncthreads();

    // ---------------- p and y ----------------
    #pragma unroll
    for (int idx = tid; idx < PAA * CH; idx += 512) {
        int c = idx & (CH - 1);
        float mn  = smin[c];
        float inv = 1.0f / (smax[c] - mn);
        float pv  = ((&sp[0][0])[idx] * (1.0f / BINSZ) - mn) * inv;
        (&sp[0][0])[idx] = pv;
        (&sy[0][0])[idx] = sqrtf(fmaxf(0.0f, 1.0f - pv * pv));
    }
    __syncthreads();

    // ---------------- Write phase: out[b,i,j,c] = y_i*p_j - p_i*y_j ------
    const int j = tid >> 3;            // 0..63
    const float4 pj = *(const float4*)&sp[j][c4];
    const float4 yj = *(const float4*)&sy[j][c4];

    float* ob = out + (size_t)b * (PAA * PAA * CH) + (size_t)j * CH + c4;
    #pragma unroll 4
    for (int i = 0; i < PAA; ++i) {
        const float4 pi = *(const float4*)&sp[i][c4];   // 8 addrs, broadcast x4
        const float4 yi = *(const float4*)&sy[i][c4];
        float4 o;
        o.x = yi.x * pj.x - pi.x * yj.x;
        o.y = yi.y * pj.y - pi.y * yj.y;
        o.z = yi.z * pj.z - pi.z * yj.z;
        o.w = yi.w * pj.w - pi.w * yj.w;
        __stcs((float4*)(ob + (size_t)i * (PAA * CH)), o);
    }
}

extern "C" void kernel_launch(void* const* d_in, const int* in_sizes, int n_in,
                              void* d_out, int out_size) {
    const float* x = (const float*)d_in[0];
    float* out = (float*)d_out;
    gaf_gadf_kernel<<<BATCH, 512>>>(x, out);
}

// round 3
// speedup vs baseline: 1.0746x; 1.0746x over previous
#include <cuda_runtime.h>

// x[256, 4096, 32] -> out[256, 64, 64, 32]  (GADF)
#define BATCH 256
#define TLEN  4096
#define CH    32
#define PAA   64
#define BINSZ 64   // TLEN / PAA

// One block per batch element, 1024 threads = 32 warps (2 CTAs/SM, occ ~81%).
//
// Read phase: warp w owns t in [128w, 128w+128) = bins 2w, 2w+1.
//   lane -> (t_off = lane>>3 in [0,4), c4 = (lane&7)*4).  Iter k loads
//   float4 at x[b, 128w + 4k + t_off, c4] -> warp reads 512B contiguous
//   (LDG.128). k<16 -> bin 2w, else bin 2w+1. Sums+min/max in float4 regs.
// Cross-lane: xor-8/16 shuffles collapse the 4 t_off copies.
// Write phase: thread owns (c4, j = (tid>>3)&63, i0 = tid>>9), i += 2,
//   STG.128 streaming, 512B contiguous per warp.
__global__ __launch_bounds__(1024, 2)
void gaf_gadf_kernel(const float* __restrict__ x, float* __restrict__ out) {
    __shared__ float sp[PAA][CH];      // bin sums -> p   (8 KB)
    __shared__ float sy[PAA][CH];      // y               (8 KB)
    __shared__ float smmn[32][36];     // per-warp per-channel min (16B-aligned rows)
    __shared__ float smmx[32][36];
    __shared__ float smin[CH];
    __shared__ float smax[CH];

    const int tid   = threadIdx.x;
    const int lane  = tid & 31;
    const int warp  = tid >> 5;        // 0..31
    const int t_off = lane >> 3;       // 0..3
    const int c4    = (lane & 7) * 4;  // channel group start
    const int b     = blockIdx.x;

    const float* xb = x + (size_t)b * (TLEN * CH);

    // ---------------- Read phase ----------------
    {
        const float* base = xb + (size_t)(128 * warp + t_off) * CH + c4;
        float4 s0 = {0,0,0,0}, s1 = {0,0,0,0};
        float4 vmin = { 3.4e38f,  3.4e38f,  3.4e38f,  3.4e38f};
        float4 vmax = {-3.4e38f, -3.4e38f, -3.4e38f, -3.4e38f};

        #pragma unroll 8
        for (int k = 0; k < 16; ++k) {
            float4 v = __ldcs((const float4*)(base + (size_t)(4 * k) * CH));
            s0.x += v.x; s0.y += v.y; s0.z += v.z; s0.w += v.w;
            vmin.x = fminf(vmin.x, v.x); vmin.y = fminf(vmin.y, v.y);
            vmin.z = fminf(vmin.z, v.z); vmin.w = fminf(vmin.w, v.w);
            vmax.x = fmaxf(vmax.x, v.x); vmax.y = fmaxf(vmax.y, v.y);
            vmax.z = fmaxf(vmax.z, v.z); vmax.w = fmaxf(vmax.w, v.w);
        }
        #pragma unroll 8
        for (int k = 16; k < 32; ++k) {
            float4 v = __ldcs((const float4*)(base + (size_t)(4 * k) * CH));
            s1.x += v.x; s1.y += v.y; s1.z += v.z; s1.w += v.w;
            vmin.x = fminf(vmin.x, v.x); vmin.y = fminf(vmin.y, v.y);
            vmin.z = fminf(vmin.z, v.z); vmin.w = fminf(vmin.w, v.w);
            vmax.x = fmaxf(vmax.x, v.x); vmax.y = fmaxf(vmax.y, v.y);
            vmax.z = fmaxf(vmax.z, v.z); vmax.w = fmaxf(vmax.w, v.w);
        }

        // Collapse the 4 t_off copies (lanes xor 8, 16).
        #pragma unroll
        for (int o = 8; o <= 16; o <<= 1) {
            s0.x += __shfl_xor_sync(~0u, s0.x, o); s0.y += __shfl_xor_sync(~0u, s0.y, o);
            s0.z += __shfl_xor_sync(~0u, s0.z, o); s0.w += __shfl_xor_sync(~0u, s0.w, o);
            s1.x += __shfl_xor_sync(~0u, s1.x, o); s1.y += __shfl_xor_sync(~0u, s1.y, o);
            s1.z += __shfl_xor_sync(~0u, s1.z, o); s1.w += __shfl_xor_sync(~0u, s1.w, o);
            vmin.x = fminf(vmin.x, __shfl_xor_sync(~0u, vmin.x, o));
            vmin.y = fminf(vmin.y, __shfl_xor_sync(~0u, vmin.y, o));
            vmin.z = fminf(vmin.z, __shfl_xor_sync(~0u, vmin.z, o));
            vmin.w = fminf(vmin.w, __shfl_xor_sync(~0u, vmin.w, o));
            vmax.x = fmaxf(vmax.x, __shfl_xor_sync(~0u, vmax.x, o));
            vmax.y = fmaxf(vmax.y, __shfl_xor_sync(~0u, vmax.y, o));
            vmax.z = fmaxf(vmax.z, __shfl_xor_sync(~0u, vmax.z, o));
            vmax.w = fmaxf(vmax.w, __shfl_xor_sync(~0u, vmax.w, o));
        }
        if (t_off == 0) {  // lanes 0..7 hold reduced values for channels c4..c4+3
            *(float4*)&sp[2 * warp + 0][c4] = s0;
            *(float4*)&sp[2 * warp + 1][c4] = s1;
            *(float4*)&smmn[warp][c4] = vmin;
            *(float4*)&smmx[warp][c4] = vmax;
        }
    }
    __syncthreads();

    // ---------------- Final min/max over 32 warps ----------------
    if (tid < CH) {
        float m = smmn[0][tid], M = smmx[0][tid];
        #pragma unroll
        for (int w = 1; w < 32; ++w) {
            m = fminf(m, smmn[w][tid]);
            M = fmaxf(M, smmx[w][tid]);
        }
        smin[tid] = m;
        smax[tid] = M;
    }
    __syncthreads();

    // ---------------- p and y ----------------
    {
        int idx = tid;                 // 1024 threads cover 2048 elems in 2 steps
        #pragma unroll
        for (int r = 0; r < 2; ++r, idx += 1024) {
            int c = idx & (CH - 1);
            float mn  = smin[c];
            float inv = 1.0f / (smax[c] - mn);
            float pv  = ((&sp[0][0])[idx] * (1.0f / BINSZ) - mn) * inv;
            (&sp[0][0])[idx] = pv;
            (&sy[0][0])[idx] = sqrtf(fmaxf(0.0f, 1.0f - pv * pv));
        }
    }
    __syncthreads();

    // ---------------- Write phase: out[b,i,j,c] = y_i*p_j - p_i*y_j ------
    const int j  = (tid >> 3) & 63;
    const int i0 = tid >> 9;           // 0 or 1; i strides by 2

    const float4 pj = *(const float4*)&sp[j][c4];
    const float4 yj = *(const float4*)&sy[j][c4];

    float* ob = out + (size_t)b * (PAA * PAA * CH) + (size_t)j * CH + c4;
    #pragma unroll 4
    for (int i = i0; i < PAA; i += 2) {
        const float4 pi = *(const float4*)&sp[i][c4];   // 8 addrs, broadcast x4
        const float4 yi = *(const float4*)&sy[i][c4];
        float4 o;
        o.x = yi.x * pj.x - pi.x * yj.x;
        o.y = yi.y * pj.y - pi.y * yj.y;
        o.z = yi.z * pj.z - pi.z * yj.z;
        o.w = yi.w * pj.w - pi.w * yj.w;
        __stcs((float4*)(ob + (size_t)i * (PAA * CH)), o);
    }
}

extern "C" void kernel_launch(void* const* d_in, const int* in_sizes, int n_in,
                              void* d_out, int out_size) {
    const float* x = (const float*)d_in[0];
    float* out = (float*)d_out;
    gaf_gadf_kernel<<<BATCH, 1024>>>(x, out);
}